// round 15
// baseline (speedup 1.0000x reference)
#include <cuda_runtime.h>
#include <cuda_bf16.h>
#include <math_constants.h>
#include <cstdint>

// Problem constants
#define BB 4
#define TT 2048
#define BT 8192          // B*T
#define DIM 1024
#define HH 16
#define DD 64            // DIM_INNER
#define DOUT 1024
#define WCH 64           // w-pipeline chunk rows
#define NWC (TT / WCH)   // 32
#define NBH (BB * HH)    // 64

// ===================== PTX helpers (non-'a' safe: sm_80+) =================
__device__ __forceinline__ uint32_t smem_u32(const void* p) {
    uint32_t a;
    asm("{ .reg .u64 t; cvta.to.shared.u64 t, %1; cvt.u32.u64 %0, t; }" : "=r"(a) : "l"(p));
    return a;
}
#define CP_ASYNC16(dst, src) \
    asm volatile("cp.async.cg.shared.global [%0], [%1], 16;" :: "r"(dst), "l"(src))
#define CP_COMMIT() asm volatile("cp.async.commit_group;" ::: "memory")
#define CP_WAIT0() asm volatile("cp.async.wait_group 0;" ::: "memory")
#define SW128(off) ((off) ^ (((off) >> 3) & 0x70))

#define LDMATRIX_X4(r0, r1, r2, r3, addr)                                     \
    asm volatile("ldmatrix.sync.aligned.m8n8.x4.shared.b16 {%0,%1,%2,%3}, [%4];" \
                 : "=r"(r0), "=r"(r1), "=r"(r2), "=r"(r3) : "r"(addr))

#define MMA_BF16(c0, c1, c2, c3, a0, a1, a2, a3, b0, b1)                      \
    asm volatile("mma.sync.aligned.m16n8k16.row.col.f32.bf16.bf16.f32 "       \
                 "{%0,%1,%2,%3}, {%4,%5,%6,%7}, {%8,%9}, {%0,%1,%2,%3};"      \
                 : "+f"(c0), "+f"(c1), "+f"(c2), "+f"(c3)                     \
                 : "r"(a0), "r"(a1), "r"(a2), "r"(a3), "r"(b0), "r"(b1))

// ---------------- scratch (device globals; no allocations allowed) -------
__device__ __nv_bfloat16 g_xh[(size_t)BT * DIM];      // x hi (bf16)
__device__ __nv_bfloat16 g_xl[(size_t)BT * DIM];      // x lo (bf16)
__device__ __nv_bfloat16 g_wh[(size_t)DIM * DIM];     // Wv^T hi : [n][k]
__device__ __nv_bfloat16 g_wl[(size_t)DIM * DIM];     // Wv^T lo : [n][k]
__device__ __nv_bfloat16 g_qkTh[HH * DIM];            // qk^T hi : [h][k]
__device__ __nv_bfloat16 g_qkTl[HH * DIM];            // qk^T lo : [h][k]
__device__ float g_v[(size_t)BT * DIM];               // v activations
__device__ float g_stT[NBH * TT];                     // scores [bh][t]
__device__ float g_gq[NBH * TT];                      // g_t = exp(st - m*)
__device__ float g_rq[NBH * TT];                      // r_t = 1 / cumsum(g)
__device__ float g_ws[BB * NWC * DIM];                // chunk sums of v*g
__device__ float g_hmean[BT * DD];                    // head-mean

// ---------------- pack_all: x split, Wv transpose+split, qk fold+split ---
__global__ void pack_all(const float* __restrict__ x,
                         const float* __restrict__ kvk,
                         const float* __restrict__ q) {
    int bx = blockIdx.x;
    int tid = threadIdx.x;
    if (bx < 8192) {                     // ---- pack_x ----
        int idx = bx * 256 + tid;        // float4 index over BT*DIM/4
        float4 a = ((const float4*)x)[idx];
        __nv_bfloat16 h0 = __float2bfloat16_rn(a.x), h1 = __float2bfloat16_rn(a.y);
        __nv_bfloat16 h2 = __float2bfloat16_rn(a.z), h3 = __float2bfloat16_rn(a.w);
        __nv_bfloat162* ph = (__nv_bfloat162*)g_xh;
        __nv_bfloat162* pl = (__nv_bfloat162*)g_xl;
        ph[idx * 2 + 0] = __nv_bfloat162(h0, h1);
        ph[idx * 2 + 1] = __nv_bfloat162(h2, h3);
        __nv_bfloat16 l0 = __float2bfloat16_rn(a.x - __bfloat162float(h0));
        __nv_bfloat16 l1 = __float2bfloat16_rn(a.y - __bfloat162float(h1));
        __nv_bfloat16 l2 = __float2bfloat16_rn(a.z - __bfloat162float(h2));
        __nv_bfloat16 l3 = __float2bfloat16_rn(a.w - __bfloat162float(h3));
        pl[idx * 2 + 0] = __nv_bfloat162(l0, l1);
        pl[idx * 2 + 1] = __nv_bfloat162(l2, l3);
    } else if (bx < 9216) {              // ---- pack_w ----
        __shared__ float tile[32][33];
        int q2 = bx - 8192;
        int bi = (q2 & 31) * 32;         // k (i) base
        int bn = (q2 >> 5) * 32;         // n base
        int tx = tid & 31, ty = tid >> 5;   // 32x8
#pragma unroll
        for (int k = 0; k < 4; k++) {
            int il = ty + k * 8;
            tile[il][tx] = kvk[(size_t)(bi + il) * 2048 + (bn + tx) * 2 + 1];
        }
        __syncthreads();
#pragma unroll
        for (int k = 0; k < 4; k++) {
            int nl = ty + k * 8;
            float a = tile[tx][nl];
            __nv_bfloat16 h = __float2bfloat16_rn(a);
            __nv_bfloat16 l = __float2bfloat16_rn(a - __bfloat162float(h));
            g_wh[(size_t)(bn + nl) * DIM + bi + tx] = h;
            g_wl[(size_t)(bn + nl) * DIM + bi + tx] = l;
        }
    } else {                             // ---- qk fold + transposed split ----
        int idx = (bx - 9216) * 256 + tid;   // over 1024*16
        int i = idx >> 4, h = idx & 15;
        const float* kp = kvk + (size_t)i * 2048 + h * 128;  // (h*64+o)*2, k=0
        const float* qp = q + h * DD;
        float s = 0.f;
#pragma unroll
        for (int o = 0; o < DD; o++) s += qp[o] * kp[o * 2];
        __nv_bfloat16 hi = __float2bfloat16_rn(s);
        g_qkTh[h * DIM + i] = hi;
        g_qkTl[h * DIM + i] = __float2bfloat16_rn(s - __bfloat162float(hi));
    }
}

// ====== fused GEMM: v = x @ Wv  AND  st = x @ qk  (split-bf16, mma.sync) ==
// Single-pass 3-product formulation: per 64-k chunk load Ah,Al,Bh,Bl once,
// accumulate Ah·Bh + Ah·Bl + Al·Bh. 16 chunks, 2-stage 64KB pipeline.
// grid (9, 64): bx<8 -> v-tile CTA (n0=bx*128, m0=by*128), 4 warps 2x2,
// warp 64x64. bx==8 -> st CTA for rows [by*128,+128), Q in the B region.
#define GV_TM 128
#define GV_TN 128
#define GV_NKC 16
#define GV_T_BYTES 16384                          // one 128x128B tile
#define GV_STAGE_BYTES (4 * GV_T_BYTES)           // Ah|Al|Bh|Bl = 64 KB
#define GV_SMEM_TOTAL (2 * GV_STAGE_BYTES)        // 128 KB

__global__ __launch_bounds__(128, 1) void gemm_vst() {
    extern __shared__ char smem[];
    uint32_t sbase = smem_u32(smem);
    int tid = threadIdx.x;
    int wid = tid >> 5, lane = tid & 31;
    int m0 = blockIdx.y * GV_TM;
    const uint32_t stage_off[2] = {0u, (uint32_t)GV_STAGE_BYTES};
    int a_row = lane & 15, a_cs = lane >> 4;
    int b_row = ((lane >> 4) << 3) + (lane & 7), b_cs = (lane >> 3) & 1;
    int gid = lane >> 2, tig = lane & 3;

    if (blockIdx.x == 8) {
        // ---------------- st path: 128 rows x 16 heads ----------------
        float acc[2][2][4];
#pragma unroll
        for (int mi = 0; mi < 2; mi++)
#pragma unroll
            for (int ni = 0; ni < 2; ni++)
#pragma unroll
                for (int j = 0; j < 4; j++) acc[mi][ni][j] = 0.f;

        auto load_chunk_st = [&](int c, uint32_t so) {
            int kc = c << 6;
#pragma unroll
            for (int i = 0; i < 8; i++) {          // Ah: 128 rows x 8 segs
                int seg = tid + (i << 7);
                int r = seg >> 3, jb = seg & 7;
                uint32_t off = SW128((uint32_t)((r << 7) + (jb << 4)));
                CP_ASYNC16(sbase + so + off,
                           g_xh + (size_t)(m0 + r) * DIM + kc + (jb << 3));
            }
#pragma unroll
            for (int i = 0; i < 8; i++) {          // Al
                int seg = tid + (i << 7);
                int r = seg >> 3, jb = seg & 7;
                uint32_t off = SW128((uint32_t)((r << 7) + (jb << 4)));
                CP_ASYNC16(sbase + so + GV_T_BYTES + off,
                           g_xl + (size_t)(m0 + r) * DIM + kc + (jb << 3));
            }
            {                                       // Qh: 16 rows x 8 segs
                int r = tid >> 3, jb = tid & 7;
                uint32_t off = SW128((uint32_t)((r << 7) + (jb << 4)));
                CP_ASYNC16(sbase + so + 2 * GV_T_BYTES + off,
                           g_qkTh + (size_t)r * DIM + kc + (jb << 3));
                CP_ASYNC16(sbase + so + 2 * GV_T_BYTES + 2048 + off,
                           g_qkTl + (size_t)r * DIM + kc + (jb << 3));
            }
            CP_COMMIT();
        };

        load_chunk_st(0, stage_off[0]);
        for (int c = 0; c < GV_NKC; c++) {
            int s = c & 1;
            CP_WAIT0();
            __syncthreads();
            if (c + 1 < GV_NKC) load_chunk_st(c + 1, stage_off[1 - s]);
            uint32_t sA_h = sbase + stage_off[s];
            uint32_t sA_l = sA_h + GV_T_BYTES;
            uint32_t sQ_h = sA_h + 2 * GV_T_BYTES;
            uint32_t sQ_l = sQ_h + 2048;
#pragma unroll
            for (int ks = 0; ks < 4; ks++) {
                uint32_t ah[2][4], al[2][4];
#pragma unroll
                for (int mi = 0; mi < 2; mi++) {
                    int row = wid * 32 + mi * 16 + a_row;
                    uint32_t off = SW128((uint32_t)((row << 7) + ((ks * 2 + a_cs) << 4)));
                    LDMATRIX_X4(ah[mi][0], ah[mi][1], ah[mi][2], ah[mi][3], sA_h + off);
                    LDMATRIX_X4(al[mi][0], al[mi][1], al[mi][2], al[mi][3], sA_l + off);
                }
                uint32_t qh[2][2], ql[2][2];
                {
                    uint32_t off = SW128((uint32_t)((b_row << 7) + ((ks * 2 + b_cs) << 4)));
                    uint32_t r0, r1, r2, r3;
                    LDMATRIX_X4(r0, r1, r2, r3, sQ_h + off);
                    qh[0][0] = r0; qh[0][1] = r1; qh[1][0] = r2; qh[1][1] = r3;
                    LDMATRIX_X4(r0, r1, r2, r3, sQ_l + off);
                    ql[0][0] = r0; ql[0][1] = r1; ql[1][0] = r2; ql[1][1] = r3;
                }
#pragma unroll
                for (int mi = 0; mi < 2; mi++)
#pragma unroll
                    for (int ni = 0; ni < 2; ni++) {
                        MMA_BF16(acc[mi][ni][0], acc[mi][ni][1], acc[mi][ni][2], acc[mi][ni][3],
                                 ah[mi][0], ah[mi][1], ah[mi][2], ah[mi][3],
                                 qh[ni][0], qh[ni][1]);
                        MMA_BF16(acc[mi][ni][0], acc[mi][ni][1], acc[mi][ni][2], acc[mi][ni][3],
                                 ah[mi][0], ah[mi][1], ah[mi][2], ah[mi][3],
                                 ql[ni][0], ql[ni][1]);
                        MMA_BF16(acc[mi][ni][0], acc[mi][ni][1], acc[mi][ni][2], acc[mi][ni][3],
                                 al[mi][0], al[mi][1], al[mi][2], al[mi][3],
                                 qh[ni][0], qh[ni][1]);
                    }
            }
        }
#pragma unroll
        for (int mi = 0; mi < 2; mi++) {
            int r = m0 + wid * 32 + mi * 16 + gid;
            int b = r >> 11;
            int t0 = r & 2047, t8 = (r + 8) & 2047;
#pragma unroll
            for (int ni = 0; ni < 2; ni++) {
                int h0 = ni * 8 + tig * 2;
                g_stT[(size_t)(b * HH + h0) * TT + t0]     = acc[mi][ni][0];
                g_stT[(size_t)(b * HH + h0 + 1) * TT + t0] = acc[mi][ni][1];
                g_stT[(size_t)(b * HH + h0) * TT + t8]     = acc[mi][ni][2];
                g_stT[(size_t)(b * HH + h0 + 1) * TT + t8] = acc[mi][ni][3];
            }
        }
        return;
    }

    // ---------------- v path: CTA tile 128x128 ----------------
    int n0 = blockIdx.x * GV_TN;
    int wm = wid >> 1;
    int wn = wid & 1;

    float acc[4][8][4];
#pragma unroll
    for (int mi = 0; mi < 4; mi++)
#pragma unroll
        for (int ni = 0; ni < 8; ni++)
#pragma unroll
            for (int j = 0; j < 4; j++) acc[mi][ni][j] = 0.f;

    auto load_chunk = [&](int c, uint32_t so) {
        int kc = c << 6;
#pragma unroll
        for (int i = 0; i < 8; i++) {               // Ah
            int seg = tid + (i << 7);
            int r = seg >> 3, jb = seg & 7;
            uint32_t off = SW128((uint32_t)((r << 7) + (jb << 4)));
            CP_ASYNC16(sbase + so + off,
                       g_xh + (size_t)(m0 + r) * DIM + kc + (jb << 3));
        }
#pragma unroll
        for (int i = 0; i < 8; i++) {               // Al
            int seg = tid + (i << 7);
            int r = seg >> 3, jb = seg & 7;
            uint32_t off = SW128((uint32_t)((r << 7) + (jb << 4)));
            CP_ASYNC16(sbase + so + GV_T_BYTES + off,
                       g_xl + (size_t)(m0 + r) * DIM + kc + (jb << 3));
        }
#pragma unroll
        for (int i = 0; i < 8; i++) {               // Bh
            int seg = tid + (i << 7);
            int r = seg >> 3, jb = seg & 7;
            uint32_t off = SW128((uint32_t)((r << 7) + (jb << 4)));
            CP_ASYNC16(sbase + so + 2 * GV_T_BYTES + off,
                       g_wh + (size_t)(n0 + r) * DIM + kc + (jb << 3));
        }
#pragma unroll
        for (int i = 0; i < 8; i++) {               // Bl
            int seg = tid + (i << 7);
            int r = seg >> 3, jb = seg & 7;
            uint32_t off = SW128((uint32_t)((r << 7) + (jb << 4)));
            CP_ASYNC16(sbase + so + 3 * GV_T_BYTES + off,
                       g_wl + (size_t)(n0 + r) * DIM + kc + (jb << 3));
        }
        CP_COMMIT();
    };

    load_chunk(0, stage_off[0]);

    for (int c = 0; c < GV_NKC; c++) {
        int s = c & 1;
        CP_WAIT0();
        __syncthreads();
        if (c + 1 < GV_NKC) load_chunk(c + 1, stage_off[1 - s]);

        uint32_t sA_h = sbase + stage_off[s];
        uint32_t sA_l = sA_h + GV_T_BYTES;
        uint32_t sB_h = sA_h + 2 * GV_T_BYTES;
        uint32_t sB_l = sA_h + 3 * GV_T_BYTES;
#pragma unroll
        for (int ks = 0; ks < 4; ks++) {
            uint32_t ah[4][4], al[4][4];
#pragma unroll
            for (int mi = 0; mi < 4; mi++) {
                int row = wm * 64 + mi * 16 + a_row;
                uint32_t off = SW128((uint32_t)((row << 7) + ((ks * 2 + a_cs) << 4)));
                LDMATRIX_X4(ah[mi][0], ah[mi][1], ah[mi][2], ah[mi][3], sA_h + off);
                LDMATRIX_X4(al[mi][0], al[mi][1], al[mi][2], al[mi][3], sA_l + off);
            }
#pragma unroll
            for (int half = 0; half < 2; half++) {
                uint32_t bh[4][2], bl[4][2];
#pragma unroll
                for (int nj = 0; nj < 2; nj++) {
                    int row = wn * 64 + (half * 2 + nj) * 16 + b_row;
                    uint32_t off = SW128((uint32_t)((row << 7) + ((ks * 2 + b_cs) << 4)));
                    uint32_t r0, r1, r2, r3;
                    LDMATRIX_X4(r0, r1, r2, r3, sB_h + off);
                    bh[nj * 2][0] = r0; bh[nj * 2][1] = r1;
                    bh[nj * 2 + 1][0] = r2; bh[nj * 2 + 1][1] = r3;
                    LDMATRIX_X4(r0, r1, r2, r3, sB_l + off);
                    bl[nj * 2][0] = r0; bl[nj * 2][1] = r1;
                    bl[nj * 2 + 1][0] = r2; bl[nj * 2 + 1][1] = r3;
                }
#pragma unroll
                for (int mi = 0; mi < 4; mi++)
#pragma unroll
                    for (int ni = 0; ni < 4; ni++) {
                        int na = half * 4 + ni;
                        MMA_BF16(acc[mi][na][0], acc[mi][na][1], acc[mi][na][2], acc[mi][na][3],
                                 ah[mi][0], ah[mi][1], ah[mi][2], ah[mi][3],
                                 bh[ni][0], bh[ni][1]);
                        MMA_BF16(acc[mi][na][0], acc[mi][na][1], acc[mi][na][2], acc[mi][na][3],
                                 ah[mi][0], ah[mi][1], ah[mi][2], ah[mi][3],
                                 bl[ni][0], bl[ni][1]);
                        MMA_BF16(acc[mi][na][0], acc[mi][na][1], acc[mi][na][2], acc[mi][na][3],
                                 al[mi][0], al[mi][1], al[mi][2], al[mi][3],
                                 bh[ni][0], bh[ni][1]);
                    }
            }
        }
    }

#pragma unroll
    for (int mi = 0; mi < 4; mi++) {
        int r0 = m0 + wm * 64 + mi * 16 + gid;
#pragma unroll
        for (int ni = 0; ni < 8; ni++) {
            int col = n0 + wn * 64 + ni * 8 + tig * 2;
            *(float2*)(g_v + (size_t)r0 * DIM + col) =
                make_float2(acc[mi][ni][0], acc[mi][ni][1]);
            *(float2*)(g_v + (size_t)(r0 + 8) * DIM + col) =
                make_float2(acc[mi][ni][2], acc[mi][ni][3]);
        }
    }
}

// ------------- k_g: per-(bh) max, g_t = exp(st-m*), r_t = 1/cumsum(g) ----
__global__ __launch_bounds__(128) void k_g() {
    int bh = blockIdx.x;                 // 64
    int tid = threadIdx.x;               // 128, each owns 16 consecutive t
    const float* stp = g_stT + (size_t)bh * TT;
    float s[16];
#pragma unroll
    for (int j = 0; j < 16; j++) s[j] = stp[tid * 16 + j];
    float lm = s[0];
#pragma unroll
    for (int j = 1; j < 16; j++) lm = fmaxf(lm, s[j]);
    __shared__ float sc[128];
    sc[tid] = lm;
    __syncthreads();
#pragma unroll
    for (int off = 64; off > 0; off >>= 1) {
        if (tid < off) sc[tid] = fmaxf(sc[tid], sc[tid + off]);
        __syncthreads();
    }
    float mstar = sc[0];
    __syncthreads();
    float g[16];
    float run = 0.f;
#pragma unroll
    for (int j = 0; j < 16; j++) { g[j] = __expf(s[j] - mstar); run += g[j]; }
    sc[tid] = run;
    __syncthreads();
#pragma unroll
    for (int off = 1; off < 128; off <<= 1) {
        float v = (tid >= off) ? sc[tid - off] : 0.f;
        __syncthreads();
        sc[tid] += v;
        __syncthreads();
    }
    float cum = (tid == 0) ? 0.f : sc[tid - 1];   // exclusive, additions-only
    float* gg = g_gq + (size_t)bh * TT + tid * 16;
    float* gr = g_rq + (size_t)bh * TT + tid * 16;
#pragma unroll
    for (int j = 0; j < 16; j++) {
        cum += g[j];
        gg[j] = g[j];
        gr[j] = __fdividef(1.f, fmaxf(cum, 1e-37f));
    }
}

// ------------- k_w1: chunk sums of v*g over 64-row chunks ----------------
__global__ __launch_bounds__(512) void k_w1() {
    int c = blockIdx.x;                  // 32
    int hq = blockIdx.y;                 // 2
    int b = blockIdx.z;                  // 4
    int tid = threadIdx.x;               // 512: hh(8) x d(64)
    int hh = tid >> 6, d = tid & 63;
    __shared__ float gs[8][64];
    gs[hh][d] = g_gq[(size_t)(b * HH + hq * 8 + hh) * TT + c * WCH + d];
    __syncthreads();
    int row0 = b * TT + c * WCH;
    const float* vp = g_v + (size_t)row0 * DIM + (hq * 8 + hh) * DD + d;
    float w = 0.f;
#pragma unroll 16
    for (int t = 0; t < WCH; t++) w += vp[(size_t)t * DIM] * gs[hh][t];
    g_ws[((b * NWC + c) << 10) + (hq * 8 + hh) * DD + d] = w;
}

// ------------- k_w3: chunk prefix + cumsum + h = w*r, fused head-mean ----
__global__ __launch_bounds__(1024) void k_w3() {
    int c = blockIdx.x;                  // 32
    int b = blockIdx.y;                  // 4
    int tid = threadIdx.x;               // 1024 = h*64+d
    int h = tid >> 6, d = tid & 63;
    __shared__ float gs[16][64];
    __shared__ float rs[16][64];
    __shared__ float red[4][16][65];     // 4-t batch, padded
    __shared__ float red2[4][4][68];     // partial head sums
    gs[h][d] = g_gq[(size_t)(b * HH + h) * TT + c * WCH + d];
    rs[h][d] = g_rq[(size_t)(b * HH + h) * TT + c * WCH + d];
    // exclusive chunk prefix computed in-place (same order as old k_w2)
    float w = 0.f;
    for (int cc = 0; cc < c; cc++) w += g_ws[((b * NWC + cc) << 10) + tid];
    int row0 = b * TT + c * WCH;
    const float* vp = g_v + (size_t)row0 * DIM + tid;
    __syncthreads();

    int k2 = tid >> 8;                   // 0..3 (t within batch)
    int hq = (tid >> 6) & 3;             // 0..3 (head quarter)
    int d2 = tid & 63;

    float vbuf[2][4];
#pragma unroll
    for (int k = 0; k < 4; k++) vbuf[0][k] = vp[(size_t)k * DIM];

    for (int t = 0; t < WCH; t += 4) {
        int cur = (t >> 2) & 1, nxt = cur ^ 1;
        if (t + 4 < WCH) {
#pragma unroll
            for (int k = 0; k < 4; k++) vbuf[nxt][k] = vp[(size_t)(t + 4 + k) * DIM];
        }
#pragma unroll
        for (int k = 0; k < 4; k++) {
            int tt = t + k;
            w += vbuf[cur][k] * gs[h][tt];
            red[k][h][d] = w * rs[h][tt];
        }
        __syncthreads();
        float p = red[k2][hq * 4 + 0][d2] + red[k2][hq * 4 + 1][d2]
                + red[k2][hq * 4 + 2][d2] + red[k2][hq * 4 + 3][d2];
        red2[k2][hq][d2] = p;
        __syncthreads();
        if (tid < 256) {
            int kk = tid >> 6, dd = tid & 63;
            float s = red2[kk][0][dd] + red2[kk][1][dd]
                    + red2[kk][2][dd] + red2[kk][3][dd];
            g_hmean[(size_t)(row0 + t + kk) * DD + dd] = s * 0.0625f;
        }
        __syncthreads();
    }
}

// ---------------- output GEMM: out = hmean @ out_w^T + b -----------------
__global__ void gemm_out(const float* __restrict__ out_w,
                         const float* __restrict__ out_b,
                         float* __restrict__ out) {
    __shared__ float Hs[64][65];
    __shared__ float Ws[64][68];
    int m0 = blockIdx.y * 64, n0 = blockIdx.x * 64;
    int tid = threadIdx.x;
    const float* hsrc = g_hmean + (size_t)m0 * DD;
    for (int i = tid; i < 64 * 64; i += 256) Hs[i >> 6][i & 63] = hsrc[i];
    for (int i = tid; i < 64 * 64; i += 256) {
        int o = i >> 6, d = i & 63;
        Ws[d][o] = out_w[(size_t)(n0 + o) * DD + d];
    }
    __syncthreads();
    int tr = tid >> 4, tc = tid & 15;
    float acc[4][4];
#pragma unroll
    for (int i = 0; i < 4; i++)
#pragma unroll
        for (int j = 0; j < 4; j++) acc[i][j] = 0.f;
#pragma unroll 8
    for (int k = 0; k < 64; k++) {
        float a[4], bv[4];
#pragma unroll
        for (int i = 0; i < 4; i++) a[i] = Hs[tr * 4 + i][k];
#pragma unroll
        for (int j = 0; j < 4; j++) bv[j] = Ws[k][tc * 4 + j];
#pragma unroll
        for (int i = 0; i < 4; i++)
#pragma unroll
            for (int j = 0; j < 4; j++) acc[i][j] += a[i] * bv[j];
    }
    float bo[4];
#pragma unroll
    for (int j = 0; j < 4; j++) bo[j] = out_b[n0 + tc * 4 + j];
#pragma unroll
    for (int i = 0; i < 4; i++) {
        float4 v4 = make_float4(acc[i][0] + bo[0], acc[i][1] + bo[1],
                                acc[i][2] + bo[2], acc[i][3] + bo[3]);
        *(float4*)(out + (size_t)(m0 + tr * 4 + i) * DOUT + n0 + tc * 4) = v4;
    }
}

// ---------------- launch -------------------------------------------------
extern "C" void kernel_launch(void* const* d_in, const int* in_sizes, int n_in,
                              void* d_out, int out_size) {
    const float* x    = (const float*)d_in[0];   // [4,2048,1024]
    const float* kvk  = (const float*)d_in[1];   // [1024,16,64,2]
    const float* q    = (const float*)d_in[2];   // [16,64]
    const float* outw = (const float*)d_in[3];   // [1024,64]
    const float* outb = (const float*)d_in[4];   // [1024]
    float* out = (float*)d_out;                  // [4,2048,1024]

    cudaFuncSetAttribute(gemm_vst, cudaFuncAttributeMaxDynamicSharedMemorySize,
                         GV_SMEM_TOTAL);

    pack_all<<<8192 + 1024 + 64, 256>>>(x, kvk, q);
    gemm_vst<<<dim3(9, BT / GV_TM), 128, GV_SMEM_TOTAL>>>();
    k_g<<<NBH, 128>>>();
    k_w1<<<dim3(NWC, 2, BB), 512>>>();
    k_w3<<<dim3(NWC, BB), 1024>>>();
    gemm_out<<<dim3(DOUT / 64, BT / 64), 256>>>(outw, outb, out);
}

// round 16
// speedup vs baseline: 1.0375x; 1.0375x over previous
#include <cuda_runtime.h>
#include <cuda_bf16.h>
#include <math_constants.h>
#include <cstdint>

// Problem constants
#define BB 4
#define TT 2048
#define BT 8192          // B*T
#define DIM 1024
#define HH 16
#define DD 64            // DIM_INNER
#define DOUT 1024
#define WCH 64           // w-pipeline chunk rows
#define NWC (TT / WCH)   // 32
#define NBH (BB * HH)    // 64

// ===================== PTX helpers (non-'a' safe: sm_80+) =================
__device__ __forceinline__ uint32_t smem_u32(const void* p) {
    uint32_t a;
    asm("{ .reg .u64 t; cvta.to.shared.u64 t, %1; cvt.u32.u64 %0, t; }" : "=r"(a) : "l"(p));
    return a;
}
#define CP_ASYNC16(dst, src) \
    asm volatile("cp.async.cg.shared.global [%0], [%1], 16;" :: "r"(dst), "l"(src))
#define CP_COMMIT() asm volatile("cp.async.commit_group;" ::: "memory")
#define CP_WAIT0() asm volatile("cp.async.wait_group 0;" ::: "memory")
#define SW128(off) ((off) ^ (((off) >> 3) & 0x70))

#define LDMATRIX_X4(r0, r1, r2, r3, addr)                                     \
    asm volatile("ldmatrix.sync.aligned.m8n8.x4.shared.b16 {%0,%1,%2,%3}, [%4];" \
                 : "=r"(r0), "=r"(r1), "=r"(r2), "=r"(r3) : "r"(addr))

#define MMA_BF16(c0, c1, c2, c3, a0, a1, a2, a3, b0, b1)                      \
    asm volatile("mma.sync.aligned.m16n8k16.row.col.f32.bf16.bf16.f32 "       \
                 "{%0,%1,%2,%3}, {%4,%5,%6,%7}, {%8,%9}, {%0,%1,%2,%3};"      \
                 : "+f"(c0), "+f"(c1), "+f"(c2), "+f"(c3)                     \
                 : "r"(a0), "r"(a1), "r"(a2), "r"(a3), "r"(b0), "r"(b1))

// ---------------- scratch (device globals; no allocations allowed) -------
__device__ __nv_bfloat16 g_xh[(size_t)BT * DIM];      // x hi (bf16)
__device__ __nv_bfloat16 g_xl[(size_t)BT * DIM];      // x lo (bf16)
__device__ __nv_bfloat16 g_wh[(size_t)DIM * DIM];     // Wv^T hi : [n][k]
__device__ __nv_bfloat16 g_wl[(size_t)DIM * DIM];     // Wv^T lo : [n][k]
__device__ __nv_bfloat16 g_qkTh[HH * DIM];            // qk^T hi : [h][k]
__device__ __nv_bfloat16 g_qkTl[HH * DIM];            // qk^T lo : [h][k]
__device__ float g_v[(size_t)BT * DIM];               // v activations
__device__ float g_stT[NBH * TT];                     // scores [bh][t]
__device__ float g_gq[NBH * TT];                      // g_t = exp(st - m*)
__device__ float g_rq[NBH * TT];                      // r_t = 1 / cumsum(g)
__device__ float g_ws[BB * NWC * DIM];                // chunk sums of v*g
__device__ float g_hmean[BT * DD];                    // head-mean

// ---------------- pack_all: x split, Wv transpose+split, qk fold+split ---
__global__ void pack_all(const float* __restrict__ x,
                         const float* __restrict__ kvk,
                         const float* __restrict__ q) {
    int bx = blockIdx.x;
    int tid = threadIdx.x;
    if (bx < 8192) {                     // ---- pack_x ----
        int idx = bx * 256 + tid;        // float4 index over BT*DIM/4
        float4 a = ((const float4*)x)[idx];
        __nv_bfloat16 h0 = __float2bfloat16_rn(a.x), h1 = __float2bfloat16_rn(a.y);
        __nv_bfloat16 h2 = __float2bfloat16_rn(a.z), h3 = __float2bfloat16_rn(a.w);
        __nv_bfloat162* ph = (__nv_bfloat162*)g_xh;
        __nv_bfloat162* pl = (__nv_bfloat162*)g_xl;
        ph[idx * 2 + 0] = __nv_bfloat162(h0, h1);
        ph[idx * 2 + 1] = __nv_bfloat162(h2, h3);
        __nv_bfloat16 l0 = __float2bfloat16_rn(a.x - __bfloat162float(h0));
        __nv_bfloat16 l1 = __float2bfloat16_rn(a.y - __bfloat162float(h1));
        __nv_bfloat16 l2 = __float2bfloat16_rn(a.z - __bfloat162float(h2));
        __nv_bfloat16 l3 = __float2bfloat16_rn(a.w - __bfloat162float(h3));
        pl[idx * 2 + 0] = __nv_bfloat162(l0, l1);
        pl[idx * 2 + 1] = __nv_bfloat162(l2, l3);
    } else if (bx < 9216) {              // ---- pack_w ----
        __shared__ float tile[32][33];
        int q2 = bx - 8192;
        int bi = (q2 & 31) * 32;         // k (i) base
        int bn = (q2 >> 5) * 32;         // n base
        int tx = tid & 31, ty = tid >> 5;   // 32x8
#pragma unroll
        for (int k = 0; k < 4; k++) {
            int il = ty + k * 8;
            tile[il][tx] = kvk[(size_t)(bi + il) * 2048 + (bn + tx) * 2 + 1];
        }
        __syncthreads();
#pragma unroll
        for (int k = 0; k < 4; k++) {
            int nl = ty + k * 8;
            float a = tile[tx][nl];
            __nv_bfloat16 h = __float2bfloat16_rn(a);
            __nv_bfloat16 l = __float2bfloat16_rn(a - __bfloat162float(h));
            g_wh[(size_t)(bn + nl) * DIM + bi + tx] = h;
            g_wl[(size_t)(bn + nl) * DIM + bi + tx] = l;
        }
    } else {                             // ---- qk fold + transposed split ----
        int idx = (bx - 9216) * 256 + tid;   // over 1024*16
        int i = idx >> 4, h = idx & 15;
        const float* kp = kvk + (size_t)i * 2048 + h * 128;  // (h*64+o)*2, k=0
        const float* qp = q + h * DD;
        float s = 0.f;
#pragma unroll
        for (int o = 0; o < DD; o++) s += qp[o] * kp[o * 2];
        __nv_bfloat16 hi = __float2bfloat16_rn(s);
        g_qkTh[h * DIM + i] = hi;
        g_qkTl[h * DIM + i] = __float2bfloat16_rn(s - __bfloat162float(hi));
    }
}

// ====== fused GEMM: v = x @ Wv  AND  st = x @ qk  (split-bf16, mma.sync) ==
// Two-phase single-fetch-of-Ah formulation:
//   phase A (steps 0-15):  load Ah,Bh,Bl once/chunk -> Ah·Bh + Ah·Bl
//   phase B (steps 16-31): load Al,Bh            -> Al·Bh
// 2-stage pipeline over a 96KB pool; 2 CTAs/SM (launch_bounds(128,2)).
// grid (9, 64): bx<8 -> v-tile CTA (n0=bx*128, m0=by*128), 4 warps 2x2,
// warp 64x64. bx==8 -> st CTA for rows [by*128,+128).
#define GV_TM 128
#define GV_TN 128
#define GV_T_BYTES 16384                          // one 128x128B tile
#define GV_STAGE_MAX (3 * GV_T_BYTES)             // phase-A stage: 48 KB
#define GV_SMEM_TOTAL (2 * GV_STAGE_MAX)          // 96 KB pool

__global__ __launch_bounds__(128, 2) void gemm_vst() {
    extern __shared__ char smem[];
    uint32_t sbase = smem_u32(smem);
    int tid = threadIdx.x;
    int wid = tid >> 5, lane = tid & 31;
    int m0 = blockIdx.y * GV_TM;
    const uint32_t stage_off[2] = {0u, (uint32_t)GV_STAGE_MAX};
    int a_row = lane & 15, a_cs = lane >> 4;
    int b_row = ((lane >> 4) << 3) + (lane & 7), b_cs = (lane >> 3) & 1;
    int gid = lane >> 2, tig = lane & 3;

    if (blockIdx.x == 8) {
        // ------- st path: 128 rows x 16 heads, 48-step 3-pass (R13 logic) ---
        float acc[2][2][4];
#pragma unroll
        for (int mi = 0; mi < 2; mi++)
#pragma unroll
            for (int ni = 0; ni < 2; ni++)
#pragma unroll
                for (int j = 0; j < 4; j++) acc[mi][ni][j] = 0.f;

        auto load_chunk_st = [&](int c, uint32_t so) {
            int p = c >> 4;
            int kc = (c & 15) << 6;
            const __nv_bfloat16* gA = (p < 2) ? g_xh : g_xl;
            const __nv_bfloat16* gQ = (p == 1) ? g_qkTl : g_qkTh;
#pragma unroll
            for (int i = 0; i < 8; i++) {          // A: 128 rows x 8 segs
                int seg = tid + (i << 7);
                int r = seg >> 3, jb = seg & 7;
                uint32_t off = SW128((uint32_t)((r << 7) + (jb << 4)));
                CP_ASYNC16(sbase + so + off,
                           gA + (size_t)(m0 + r) * DIM + kc + (jb << 3));
            }
            {                                       // Q: 16 rows x 8 segs
                int r = tid >> 3, jb = tid & 7;
                uint32_t off = SW128((uint32_t)((r << 7) + (jb << 4)));
                CP_ASYNC16(sbase + so + GV_T_BYTES + off,
                           gQ + (size_t)r * DIM + kc + (jb << 3));
            }
            CP_COMMIT();
        };

        load_chunk_st(0, stage_off[0]);
        for (int c = 0; c < 48; c++) {
            int s = c & 1;
            CP_WAIT0();
            __syncthreads();
            if (c + 1 < 48) load_chunk_st(c + 1, stage_off[1 - s]);
            uint32_t abase = sbase + stage_off[s];
            uint32_t qbase = abase + GV_T_BYTES;
#pragma unroll
            for (int ks = 0; ks < 4; ks++) {
                uint32_t afr[2][4];
#pragma unroll
                for (int mi = 0; mi < 2; mi++) {
                    int row = wid * 32 + mi * 16 + a_row;
                    uint32_t off = SW128((uint32_t)((row << 7) + ((ks * 2 + a_cs) << 4)));
                    LDMATRIX_X4(afr[mi][0], afr[mi][1], afr[mi][2], afr[mi][3],
                                abase + off);
                }
                uint32_t bq[2][2];
                {
                    uint32_t off = SW128((uint32_t)((b_row << 7) + ((ks * 2 + b_cs) << 4)));
                    uint32_t r0, r1, r2, r3;
                    LDMATRIX_X4(r0, r1, r2, r3, qbase + off);
                    bq[0][0] = r0; bq[0][1] = r1;
                    bq[1][0] = r2; bq[1][1] = r3;
                }
#pragma unroll
                for (int mi = 0; mi < 2; mi++)
#pragma unroll
                    for (int ni = 0; ni < 2; ni++)
                        MMA_BF16(acc[mi][ni][0], acc[mi][ni][1], acc[mi][ni][2], acc[mi][ni][3],
                                 afr[mi][0], afr[mi][1], afr[mi][2], afr[mi][3],
                                 bq[ni][0], bq[ni][1]);
            }
        }
#pragma unroll
        for (int mi = 0; mi < 2; mi++) {
            int r = m0 + wid * 32 + mi * 16 + gid;
            int b = r >> 11;
            int t0 = r & 2047, t8 = (r + 8) & 2047;
#pragma unroll
            for (int ni = 0; ni < 2; ni++) {
                int h0 = ni * 8 + tig * 2;
                g_stT[(size_t)(b * HH + h0) * TT + t0]     = acc[mi][ni][0];
                g_stT[(size_t)(b * HH + h0 + 1) * TT + t0] = acc[mi][ni][1];
                g_stT[(size_t)(b * HH + h0) * TT + t8]     = acc[mi][ni][2];
                g_stT[(size_t)(b * HH + h0 + 1) * TT + t8] = acc[mi][ni][3];
            }
        }
        return;
    }

    // ---------------- v path: CTA tile 128x128, two-phase ----------------
    int n0 = blockIdx.x * GV_TN;
    int wm = wid >> 1;
    int wn = wid & 1;

    float acc[4][8][4];
#pragma unroll
    for (int mi = 0; mi < 4; mi++)
#pragma unroll
        for (int ni = 0; ni < 8; ni++)
#pragma unroll
            for (int j = 0; j < 4; j++) acc[mi][ni][j] = 0.f;

    // step < 16: phase A (Ah + Bh + Bl); step >= 16: phase B (Al + Bh)
    auto load_step = [&](int step, uint32_t so) {
        int kc = (step & 15) << 6;
        bool phA = step < 16;
        const __nv_bfloat16* gA = phA ? g_xh : g_xl;
#pragma unroll
        for (int i = 0; i < 8; i++) {               // A tile
            int seg = tid + (i << 7);
            int r = seg >> 3, jb = seg & 7;
            uint32_t off = SW128((uint32_t)((r << 7) + (jb << 4)));
            CP_ASYNC16(sbase + so + off,
                       gA + (size_t)(m0 + r) * DIM + kc + (jb << 3));
        }
#pragma unroll
        for (int i = 0; i < 8; i++) {               // Bh tile
            int seg = tid + (i << 7);
            int r = seg >> 3, jb = seg & 7;
            uint32_t off = SW128((uint32_t)((r << 7) + (jb << 4)));
            CP_ASYNC16(sbase + so + GV_T_BYTES + off,
                       g_wh + (size_t)(n0 + r) * DIM + kc + (jb << 3));
        }
        if (phA) {
#pragma unroll
            for (int i = 0; i < 8; i++) {           // Bl tile (phase A only)
                int seg = tid + (i << 7);
                int r = seg >> 3, jb = seg & 7;
                uint32_t off = SW128((uint32_t)((r << 7) + (jb << 4)));
                CP_ASYNC16(sbase + so + 2 * GV_T_BYTES + off,
                           g_wl + (size_t)(n0 + r) * DIM + kc + (jb << 3));
            }
        }
        CP_COMMIT();
    };

    load_step(0, stage_off[0]);

    for (int step = 0; step < 32; step++) {
        int s = step & 1;
        CP_WAIT0();
        __syncthreads();
        if (step + 1 < 32) load_step(step + 1, stage_off[1 - s]);

        bool phA = step < 16;
        uint32_t sA = sbase + stage_off[s];
        uint32_t sBh = sA + GV_T_BYTES;
        uint32_t sBl = sA + 2 * GV_T_BYTES;
#pragma unroll
        for (int ks = 0; ks < 4; ks++) {
            uint32_t afr[4][4];
#pragma unroll
            for (int mi = 0; mi < 4; mi++) {
                int row = wm * 64 + mi * 16 + a_row;
                uint32_t off = SW128((uint32_t)((row << 7) + ((ks * 2 + a_cs) << 4)));
                LDMATRIX_X4(afr[mi][0], afr[mi][1], afr[mi][2], afr[mi][3], sA + off);
            }
#pragma unroll
            for (int half = 0; half < 2; half++) {
                uint32_t bh[4][2];
#pragma unroll
                for (int nj = 0; nj < 2; nj++) {
                    int row = wn * 64 + (half * 2 + nj) * 16 + b_row;
                    uint32_t off = SW128((uint32_t)((row << 7) + ((ks * 2 + b_cs) << 4)));
                    uint32_t r0, r1, r2, r3;
                    LDMATRIX_X4(r0, r1, r2, r3, sBh + off);
                    bh[nj * 2][0] = r0; bh[nj * 2][1] = r1;
                    bh[nj * 2 + 1][0] = r2; bh[nj * 2 + 1][1] = r3;
                }
#pragma unroll
                for (int mi = 0; mi < 4; mi++)
#pragma unroll
                    for (int ni = 0; ni < 4; ni++) {
                        int na = half * 4 + ni;
                        MMA_BF16(acc[mi][na][0], acc[mi][na][1], acc[mi][na][2], acc[mi][na][3],
                                 afr[mi][0], afr[mi][1], afr[mi][2], afr[mi][3],
                                 bh[ni][0], bh[ni][1]);
                    }
                if (phA) {
                    uint32_t bl[4][2];
#pragma unroll
                    for (int nj = 0; nj < 2; nj++) {
                        int row = wn * 64 + (half * 2 + nj) * 16 + b_row;
                        uint32_t off = SW128((uint32_t)((row << 7) + ((ks * 2 + b_cs) << 4)));
                        uint32_t r0, r1, r2, r3;
                        LDMATRIX_X4(r0, r1, r2, r3, sBl + off);
                        bl[nj * 2][0] = r0; bl[nj * 2][1] = r1;
                        bl[nj * 2 + 1][0] = r2; bl[nj * 2 + 1][1] = r3;
                    }
#pragma unroll
                    for (int mi = 0; mi < 4; mi++)
#pragma unroll
                        for (int ni = 0; ni < 4; ni++) {
                            int na = half * 4 + ni;
                            MMA_BF16(acc[mi][na][0], acc[mi][na][1], acc[mi][na][2], acc[mi][na][3],
                                     afr[mi][0], afr[mi][1], afr[mi][2], afr[mi][3],
                                     bl[ni][0], bl[ni][1]);
                        }
                }
            }
        }
    }

#pragma unroll
    for (int mi = 0; mi < 4; mi++) {
        int r0 = m0 + wm * 64 + mi * 16 + gid;
#pragma unroll
        for (int ni = 0; ni < 8; ni++) {
            int col = n0 + wn * 64 + ni * 8 + tig * 2;
            *(float2*)(g_v + (size_t)r0 * DIM + col) =
                make_float2(acc[mi][ni][0], acc[mi][ni][1]);
            *(float2*)(g_v + (size_t)(r0 + 8) * DIM + col) =
                make_float2(acc[mi][ni][2], acc[mi][ni][3]);
        }
    }
}

// ------------- k_g: per-(bh) max, g_t = exp(st-m*), r_t = 1/cumsum(g) ----
__global__ __launch_bounds__(128) void k_g() {
    int bh = blockIdx.x;                 // 64
    int tid = threadIdx.x;               // 128, each owns 16 consecutive t
    const float* stp = g_stT + (size_t)bh * TT;
    float s[16];
#pragma unroll
    for (int j = 0; j < 16; j++) s[j] = stp[tid * 16 + j];
    float lm = s[0];
#pragma unroll
    for (int j = 1; j < 16; j++) lm = fmaxf(lm, s[j]);
    __shared__ float sc[128];
    sc[tid] = lm;
    __syncthreads();
#pragma unroll
    for (int off = 64; off > 0; off >>= 1) {
        if (tid < off) sc[tid] = fmaxf(sc[tid], sc[tid + off]);
        __syncthreads();
    }
    float mstar = sc[0];
    __syncthreads();
    float g[16];
    float run = 0.f;
#pragma unroll
    for (int j = 0; j < 16; j++) { g[j] = __expf(s[j] - mstar); run += g[j]; }
    sc[tid] = run;
    __syncthreads();
#pragma unroll
    for (int off = 1; off < 128; off <<= 1) {
        float v = (tid >= off) ? sc[tid - off] : 0.f;
        __syncthreads();
        sc[tid] += v;
        __syncthreads();
    }
    float cum = (tid == 0) ? 0.f : sc[tid - 1];   // exclusive, additions-only
    float* gg = g_gq + (size_t)bh * TT + tid * 16;
    float* gr = g_rq + (size_t)bh * TT + tid * 16;
#pragma unroll
    for (int j = 0; j < 16; j++) {
        cum += g[j];
        gg[j] = g[j];
        gr[j] = __fdividef(1.f, fmaxf(cum, 1e-37f));
    }
}

// ------------- k_w1: chunk sums of v*g over 64-row chunks ----------------
__global__ __launch_bounds__(512) void k_w1() {
    int c = blockIdx.x;                  // 32
    int hq = blockIdx.y;                 // 2
    int b = blockIdx.z;                  // 4
    int tid = threadIdx.x;               // 512: hh(8) x d(64)
    int hh = tid >> 6, d = tid & 63;
    __shared__ float gs[8][64];
    gs[hh][d] = g_gq[(size_t)(b * HH + hq * 8 + hh) * TT + c * WCH + d];
    __syncthreads();
    int row0 = b * TT + c * WCH;
    const float* vp = g_v + (size_t)row0 * DIM + (hq * 8 + hh) * DD + d;
    float w = 0.f;
#pragma unroll 8
    for (int t = 0; t < WCH; t++) w += vp[(size_t)t * DIM] * gs[hh][t];
    g_ws[((b * NWC + c) << 10) + (hq * 8 + hh) * DD + d] = w;
}

// ------------- k_w3: chunk prefix + cumsum + h = w*r, fused head-mean ----
__global__ __launch_bounds__(1024) void k_w3() {
    int c = blockIdx.x;                  // 32
    int b = blockIdx.y;                  // 4
    int tid = threadIdx.x;               // 1024 = h*64+d
    int h = tid >> 6, d = tid & 63;
    __shared__ float gs[16][64];
    __shared__ float rs[16][64];
    __shared__ float red[4][16][65];     // 4-t batch, padded
    __shared__ float red2[4][4][68];     // partial head sums
    gs[h][d] = g_gq[(size_t)(b * HH + h) * TT + c * WCH + d];
    rs[h][d] = g_rq[(size_t)(b * HH + h) * TT + c * WCH + d];
    // exclusive chunk prefix computed in-place (same order as old k_w2)
    float w = 0.f;
    for (int cc = 0; cc < c; cc++) w += g_ws[((b * NWC + cc) << 10) + tid];
    int row0 = b * TT + c * WCH;
    const float* vp = g_v + (size_t)row0 * DIM + tid;
    __syncthreads();

    int k2 = tid >> 8;                   // 0..3 (t within batch)
    int hq = (tid >> 6) & 3;             // 0..3 (head quarter)
    int d2 = tid & 63;

    float vbuf[2][4];
#pragma unroll
    for (int k = 0; k < 4; k++) vbuf[0][k] = vp[(size_t)k * DIM];

    for (int t = 0; t < WCH; t += 4) {
        int cur = (t >> 2) & 1, nxt = cur ^ 1;
        if (t + 4 < WCH) {
#pragma unroll
            for (int k = 0; k < 4; k++) vbuf[nxt][k] = vp[(size_t)(t + 4 + k) * DIM];
        }
#pragma unroll
        for (int k = 0; k < 4; k++) {
            int tt = t + k;
            w += vbuf[cur][k] * gs[h][tt];
            red[k][h][d] = w * rs[h][tt];
        }
        __syncthreads();
        float p = red[k2][hq * 4 + 0][d2] + red[k2][hq * 4 + 1][d2]
                + red[k2][hq * 4 + 2][d2] + red[k2][hq * 4 + 3][d2];
        red2[k2][hq][d2] = p;
        __syncthreads();
        if (tid < 256) {
            int kk = tid >> 6, dd = tid & 63;
            float s = red2[kk][0][dd] + red2[kk][1][dd]
                    + red2[kk][2][dd] + red2[kk][3][dd];
            g_hmean[(size_t)(row0 + t + kk) * DD + dd] = s * 0.0625f;
        }
        __syncthreads();
    }
}

// ---------------- output GEMM: out = hmean @ out_w^T + b -----------------
__global__ void gemm_out(const float* __restrict__ out_w,
                         const float* __restrict__ out_b,
                         float* __restrict__ out) {
    __shared__ float Hs[64][65];
    __shared__ float Ws[64][68];
    int m0 = blockIdx.y * 64, n0 = blockIdx.x * 64;
    int tid = threadIdx.x;
    const float* hsrc = g_hmean + (size_t)m0 * DD;
    for (int i = tid; i < 64 * 64; i += 256) Hs[i >> 6][i & 63] = hsrc[i];
    for (int i = tid; i < 64 * 64; i += 256) {
        int o = i >> 6, d = i & 63;
        Ws[d][o] = out_w[(size_t)(n0 + o) * DD + d];
    }
    __syncthreads();
    int tr = tid >> 4, tc = tid & 15;
    float acc[4][4];
#pragma unroll
    for (int i = 0; i < 4; i++)
#pragma unroll
        for (int j = 0; j < 4; j++) acc[i][j] = 0.f;
#pragma unroll 8
    for (int k = 0; k < 64; k++) {
        float a[4], bv[4];
#pragma unroll
        for (int i = 0; i < 4; i++) a[i] = Hs[tr * 4 + i][k];
#pragma unroll
        for (int j = 0; j < 4; j++) bv[j] = Ws[k][tc * 4 + j];
#pragma unroll
        for (int i = 0; i < 4; i++)
#pragma unroll
            for (int j = 0; j < 4; j++) acc[i][j] += a[i] * bv[j];
    }
    float bo[4];
#pragma unroll
    for (int j = 0; j < 4; j++) bo[j] = out_b[n0 + tc * 4 + j];
#pragma unroll
    for (int i = 0; i < 4; i++) {
        float4 v4 = make_float4(acc[i][0] + bo[0], acc[i][1] + bo[1],
                                acc[i][2] + bo[2], acc[i][3] + bo[3]);
        *(float4*)(out + (size_t)(m0 + tr * 4 + i) * DOUT + n0 + tc * 4) = v4;
    }
}

// ---------------- launch -------------------------------------------------
extern "C" void kernel_launch(void* const* d_in, const int* in_sizes, int n_in,
                              void* d_out, int out_size) {
    const float* x    = (const float*)d_in[0];   // [4,2048,1024]
    const float* kvk  = (const float*)d_in[1];   // [1024,16,64,2]
    const float* q    = (const float*)d_in[2];   // [16,64]
    const float* outw = (const float*)d_in[3];   // [1024,64]
    const float* outb = (const float*)d_in[4];   // [1024]
    float* out = (float*)d_out;                  // [4,2048,1024]

    cudaFuncSetAttribute(gemm_vst, cudaFuncAttributeMaxDynamicSharedMemorySize,
                         GV_SMEM_TOTAL);

    pack_all<<<8192 + 1024 + 64, 256>>>(x, kvk, q);
    gemm_vst<<<dim3(9, BT / GV_TM), 128, GV_SMEM_TOTAL>>>();
    k_g<<<NBH, 128>>>();
    k_w1<<<dim3(NWC, 2, BB), 512>>>();
    k_w3<<<dim3(NWC, BB), 1024>>>();
    gemm_out<<<dim3(DOUT / 64, BT / 64), 256>>>(outw, outb, out);
}

// round 17
// speedup vs baseline: 1.4541x; 1.4015x over previous
#include <cuda_runtime.h>
#include <cuda_bf16.h>
#include <math_constants.h>
#include <cstdint>

// Problem constants
#define BB 4
#define TT 2048
#define BT 8192          // B*T
#define DIM 1024
#define HH 16
#define DD 64            // DIM_INNER
#define DOUT 1024
#define WCH 64           // w-pipeline chunk rows
#define NWC (TT / WCH)   // 32
#define NBH (BB * HH)    // 64

// ===================== PTX helpers (non-'a' safe: sm_80+) =================
__device__ __forceinline__ uint32_t smem_u32(const void* p) {
    uint32_t a;
    asm("{ .reg .u64 t; cvta.to.shared.u64 t, %1; cvt.u32.u64 %0, t; }" : "=r"(a) : "l"(p));
    return a;
}
#define CP_ASYNC16(dst, src) \
    asm volatile("cp.async.cg.shared.global [%0], [%1], 16;" :: "r"(dst), "l"(src))
#define CP_COMMIT() asm volatile("cp.async.commit_group;" ::: "memory")
#define CP_WAIT1() asm volatile("cp.async.wait_group 1;" ::: "memory")
#define CP_WAIT0() asm volatile("cp.async.wait_group 0;" ::: "memory")
#define SW128(off) ((off) ^ (((off) >> 3) & 0x70))

#define LDMATRIX_X4(r0, r1, r2, r3, addr)                                     \
    asm volatile("ldmatrix.sync.aligned.m8n8.x4.shared.b16 {%0,%1,%2,%3}, [%4];" \
                 : "=r"(r0), "=r"(r1), "=r"(r2), "=r"(r3) : "r"(addr))

#define MMA_BF16(c0, c1, c2, c3, a0, a1, a2, a3, b0, b1)                      \
    asm volatile("mma.sync.aligned.m16n8k16.row.col.f32.bf16.bf16.f32 "       \
                 "{%0,%1,%2,%3}, {%4,%5,%6,%7}, {%8,%9}, {%0,%1,%2,%3};"      \
                 : "+f"(c0), "+f"(c1), "+f"(c2), "+f"(c3)                     \
                 : "r"(a0), "r"(a1), "r"(a2), "r"(a3), "r"(b0), "r"(b1))

// ---------------- scratch (device globals; no allocations allowed) -------
__device__ __nv_bfloat16 g_xh[(size_t)BT * DIM];      // x hi (bf16)
__device__ __nv_bfloat16 g_xl[(size_t)BT * DIM];      // x lo (bf16)
__device__ __nv_bfloat16 g_wh[(size_t)DIM * DIM];     // Wv^T hi : [n][k]
__device__ __nv_bfloat16 g_wl[(size_t)DIM * DIM];     // Wv^T lo : [n][k]
__device__ __nv_bfloat16 g_qkTh[HH * DIM];            // qk^T hi : [h][k]
__device__ __nv_bfloat16 g_qkTl[HH * DIM];            // qk^T lo : [h][k]
__device__ float g_v[(size_t)BT * DIM];               // v activations
__device__ float g_stT[NBH * TT];                     // scores [bh][t]
__device__ float g_gq[NBH * TT];                      // g_t = exp(st - m*)
__device__ float g_rq[NBH * TT];                      // r_t = 1 / cumsum(g)
__device__ float g_ws[BB * NWC * DIM];                // chunk sums of v*g
__device__ float g_hmean[BT * DD];                    // head-mean

// ---------------- pack_all: x split, Wv transpose+split, qk fold+split ---
// grid: [0,2048) pack_x (4 float4/thread); [2048,3072) pack_w; [3072,3136) qk.
__global__ void pack_all(const float* __restrict__ x,
                         const float* __restrict__ kvk,
                         const float* __restrict__ q) {
    int bx = blockIdx.x;
    int tid = threadIdx.x;
    if (bx < 2048) {                     // ---- pack_x: 4 f4 per thread ----
        __nv_bfloat162* ph = (__nv_bfloat162*)g_xh;
        __nv_bfloat162* pl = (__nv_bfloat162*)g_xl;
#pragma unroll
        for (int j = 0; j < 4; j++) {
            int idx = bx * 1024 + j * 256 + tid;    // f4 index over BT*DIM/4
            float4 a = ((const float4*)x)[idx];
            __nv_bfloat16 h0 = __float2bfloat16_rn(a.x), h1 = __float2bfloat16_rn(a.y);
            __nv_bfloat16 h2 = __float2bfloat16_rn(a.z), h3 = __float2bfloat16_rn(a.w);
            ph[idx * 2 + 0] = __nv_bfloat162(h0, h1);
            ph[idx * 2 + 1] = __nv_bfloat162(h2, h3);
            __nv_bfloat16 l0 = __float2bfloat16_rn(a.x - __bfloat162float(h0));
            __nv_bfloat16 l1 = __float2bfloat16_rn(a.y - __bfloat162float(h1));
            __nv_bfloat16 l2 = __float2bfloat16_rn(a.z - __bfloat162float(h2));
            __nv_bfloat16 l3 = __float2bfloat16_rn(a.w - __bfloat162float(h3));
            pl[idx * 2 + 0] = __nv_bfloat162(l0, l1);
            pl[idx * 2 + 1] = __nv_bfloat162(l2, l3);
        }
    } else if (bx < 3072) {              // ---- pack_w ----
        __shared__ float tile[32][33];
        int q2 = bx - 2048;
        int bi = (q2 & 31) * 32;         // k (i) base
        int bn = (q2 >> 5) * 32;         // n base
        int tx = tid & 31, ty = tid >> 5;   // 32x8
#pragma unroll
        for (int k = 0; k < 4; k++) {
            int il = ty + k * 8;
            tile[il][tx] = kvk[(size_t)(bi + il) * 2048 + (bn + tx) * 2 + 1];
        }
        __syncthreads();
#pragma unroll
        for (int k = 0; k < 4; k++) {
            int nl = ty + k * 8;
            float a = tile[tx][nl];
            __nv_bfloat16 h = __float2bfloat16_rn(a);
            __nv_bfloat16 l = __float2bfloat16_rn(a - __bfloat162float(h));
            g_wh[(size_t)(bn + nl) * DIM + bi + tx] = h;
            g_wl[(size_t)(bn + nl) * DIM + bi + tx] = l;
        }
    } else {                             // ---- qk fold + transposed split ----
        int idx = (bx - 3072) * 256 + tid;   // over 1024*16
        int i = idx >> 4, h = idx & 15;
        const float* kp = kvk + (size_t)i * 2048 + h * 128;  // (h*64+o)*2, k=0
        const float* qp = q + h * DD;
        float s = 0.f;
#pragma unroll
        for (int o = 0; o < DD; o++) s += qp[o] * kp[o * 2];
        __nv_bfloat16 hi = __float2bfloat16_rn(s);
        g_qkTh[h * DIM + i] = hi;
        g_qkTl[h * DIM + i] = __float2bfloat16_rn(s - __bfloat162float(hi));
    }
}

// ====== fused GEMM: v = x @ Wv  AND  st = x @ qk  (split-bf16, mma.sync) ==
// PROVEN R13 configuration: 3-stage cp.async pipeline, CP_WAIT1 (prefetch
// distance 2), 48 chunks of 32KB (3 sequential hi/lo passes), 2 CTAs/SM.
// grid (9, 64): bx<8 -> v-tile CTA (n0=bx*128, m0=by*128), 4 warps 2x2,
// warp 64x64. bx==8 -> st CTA for rows [by*128, +128), Q in the Q region.
#define GV_TM 128
#define GV_TN 128
#define GV_NCHUNK 48
#define GV_A_BYTES (GV_TM * 128)                 // 16 KB
#define GV_B_BYTES (GV_TN * 128)                 // 16 KB
#define GV_Q_BYTES (16 * 128)                    // 2 KB
#define GV_STAGE_BYTES (GV_A_BYTES + GV_B_BYTES + GV_Q_BYTES) // 34816
#define GV_SMEM_TOTAL (3 * GV_STAGE_BYTES)       // 104448

__global__ __launch_bounds__(128, 2) void gemm_vst() {
    extern __shared__ char smem[];
    uint32_t sbase = smem_u32(smem);
    int tid = threadIdx.x;
    int wid = tid >> 5, lane = tid & 31;
    int m0 = blockIdx.y * GV_TM;
    const uint32_t stage_off[3] = {0u, (uint32_t)GV_STAGE_BYTES, (uint32_t)(2 * GV_STAGE_BYTES)};
    int a_row = lane & 15, a_cs = lane >> 4;
    int b_row = ((lane >> 4) << 3) + (lane & 7), b_cs = (lane >> 3) & 1;
    int gid = lane >> 2, tig = lane & 3;

    if (blockIdx.x == 8) {
        // ---------------- st path: 128 rows x 16 heads ----------------
        float acc[2][2][4];
#pragma unroll
        for (int mi = 0; mi < 2; mi++)
#pragma unroll
            for (int ni = 0; ni < 2; ni++)
#pragma unroll
                for (int j = 0; j < 4; j++) acc[mi][ni][j] = 0.f;

        auto load_chunk_st = [&](int c, uint32_t so) {
            int p = c >> 4;
            int kc = (c & 15) << 6;
            const __nv_bfloat16* gA = (p < 2) ? g_xh : g_xl;
            const __nv_bfloat16* gQ = (p == 1) ? g_qkTl : g_qkTh;
#pragma unroll
            for (int i = 0; i < 8; i++) {          // A: 128 rows x 8 segs
                int seg = tid + (i << 7);
                int r = seg >> 3, jb = seg & 7;
                uint32_t off = SW128((uint32_t)((r << 7) + (jb << 4)));
                CP_ASYNC16(sbase + so + off,
                           gA + (size_t)(m0 + r) * DIM + kc + (jb << 3));
            }
            {                                       // Q: 16 rows x 8 segs
                int r = tid >> 3, jb = tid & 7;
                uint32_t off = SW128((uint32_t)((r << 7) + (jb << 4)));
                CP_ASYNC16(sbase + so + GV_A_BYTES + GV_B_BYTES + off,
                           gQ + (size_t)r * DIM + kc + (jb << 3));
            }
            CP_COMMIT();
        };

        load_chunk_st(0, stage_off[0]);
        load_chunk_st(1, stage_off[1]);
        for (int c = 0; c < GV_NCHUNK; c++) {
            int s = c % 3;
            if (c < GV_NCHUNK - 1) CP_WAIT1(); else CP_WAIT0();
            __syncthreads();
            if (c + 2 < GV_NCHUNK) load_chunk_st(c + 2, stage_off[(c + 2) % 3]);
            uint32_t abase = sbase + stage_off[s];
            uint32_t qbase = sbase + stage_off[s] + GV_A_BYTES + GV_B_BYTES;
#pragma unroll
            for (int ks = 0; ks < 4; ks++) {
                uint32_t afr[2][4];
#pragma unroll
                for (int mi = 0; mi < 2; mi++) {
                    int row = wid * 32 + mi * 16 + a_row;
                    uint32_t off = SW128((uint32_t)((row << 7) + ((ks * 2 + a_cs) << 4)));
                    LDMATRIX_X4(afr[mi][0], afr[mi][1], afr[mi][2], afr[mi][3],
                                abase + off);
                }
                uint32_t bq[2][2];
                {
                    uint32_t off = SW128((uint32_t)((b_row << 7) + ((ks * 2 + b_cs) << 4)));
                    uint32_t r0, r1, r2, r3;
                    LDMATRIX_X4(r0, r1, r2, r3, qbase + off);
                    bq[0][0] = r0; bq[0][1] = r1;
                    bq[1][0] = r2; bq[1][1] = r3;
                }
#pragma unroll
                for (int mi = 0; mi < 2; mi++)
#pragma unroll
                    for (int ni = 0; ni < 2; ni++)
                        MMA_BF16(acc[mi][ni][0], acc[mi][ni][1], acc[mi][ni][2], acc[mi][ni][3],
                                 afr[mi][0], afr[mi][1], afr[mi][2], afr[mi][3],
                                 bq[ni][0], bq[ni][1]);
            }
        }
#pragma unroll
        for (int mi = 0; mi < 2; mi++) {
            int r = m0 + wid * 32 + mi * 16 + gid;
            int b = r >> 11;
            int t0 = r & 2047, t8 = (r + 8) & 2047;
#pragma unroll
            for (int ni = 0; ni < 2; ni++) {
                int h0 = ni * 8 + tig * 2;
                g_stT[(size_t)(b * HH + h0) * TT + t0]     = acc[mi][ni][0];
                g_stT[(size_t)(b * HH + h0 + 1) * TT + t0] = acc[mi][ni][1];
                g_stT[(size_t)(b * HH + h0) * TT + t8]     = acc[mi][ni][2];
                g_stT[(size_t)(b * HH + h0 + 1) * TT + t8] = acc[mi][ni][3];
            }
        }
        return;
    }

    // ---------------- v path: CTA tile 128x128 ----------------
    int n0 = blockIdx.x * GV_TN;
    int wm = wid >> 1;
    int wn = wid & 1;

    float acc[4][8][4];
#pragma unroll
    for (int mi = 0; mi < 4; mi++)
#pragma unroll
        for (int ni = 0; ni < 8; ni++)
#pragma unroll
            for (int j = 0; j < 4; j++) acc[mi][ni][j] = 0.f;

    auto load_chunk = [&](int c, uint32_t so) {
        int p = c >> 4;
        int kc = (c & 15) << 6;
        const __nv_bfloat16* gA = (p < 2) ? g_xh : g_xl;
        const __nv_bfloat16* gB = (p == 1) ? g_wl : g_wh;
#pragma unroll
        for (int i = 0; i < 16; i++) {
            int seg = tid + (i << 7);
            if (seg < 1024) {
                int r = seg >> 3, jb = seg & 7;
                uint32_t off = SW128((uint32_t)((r << 7) + (jb << 4)));
                CP_ASYNC16(sbase + so + off,
                           gA + (size_t)(m0 + r) * DIM + kc + (jb << 3));
            } else {
                int s2 = seg - 1024;
                int n = s2 >> 3, jb = s2 & 7;
                uint32_t off = SW128((uint32_t)((n << 7) + (jb << 4)));
                CP_ASYNC16(sbase + so + GV_A_BYTES + off,
                           gB + (size_t)(n0 + n) * DIM + kc + (jb << 3));
            }
        }
        CP_COMMIT();
    };

    load_chunk(0, stage_off[0]);
    load_chunk(1, stage_off[1]);

    for (int c = 0; c < GV_NCHUNK; c++) {
        int s = c % 3;
        if (c < GV_NCHUNK - 1) CP_WAIT1(); else CP_WAIT0();
        __syncthreads();
        if (c + 2 < GV_NCHUNK) load_chunk(c + 2, stage_off[(c + 2) % 3]);

        uint32_t abase = sbase + stage_off[s];
        uint32_t bbase = sbase + stage_off[s] + GV_A_BYTES;
#pragma unroll
        for (int ks = 0; ks < 4; ks++) {
            uint32_t afr[4][4];
#pragma unroll
            for (int mi = 0; mi < 4; mi++) {
                int row = wm * 64 + mi * 16 + a_row;
                uint32_t off = SW128((uint32_t)((row << 7) + ((ks * 2 + a_cs) << 4)));
                LDMATRIX_X4(afr[mi][0], afr[mi][1], afr[mi][2], afr[mi][3],
                            abase + off);
            }
            uint32_t bfr[8][2];
#pragma unroll
            for (int nj = 0; nj < 4; nj++) {
                int row = wn * 64 + nj * 16 + b_row;
                uint32_t off = SW128((uint32_t)((row << 7) + ((ks * 2 + b_cs) << 4)));
                uint32_t r0, r1, r2, r3;
                LDMATRIX_X4(r0, r1, r2, r3, bbase + off);
                bfr[nj * 2 + 0][0] = r0; bfr[nj * 2 + 0][1] = r1;
                bfr[nj * 2 + 1][0] = r2; bfr[nj * 2 + 1][1] = r3;
            }
#pragma unroll
            for (int mi = 0; mi < 4; mi++)
#pragma unroll
                for (int ni = 0; ni < 8; ni++)
                    MMA_BF16(acc[mi][ni][0], acc[mi][ni][1], acc[mi][ni][2], acc[mi][ni][3],
                             afr[mi][0], afr[mi][1], afr[mi][2], afr[mi][3],
                             bfr[ni][0], bfr[ni][1]);
        }
    }

#pragma unroll
    for (int mi = 0; mi < 4; mi++) {
        int r0 = m0 + wm * 64 + mi * 16 + gid;
#pragma unroll
        for (int ni = 0; ni < 8; ni++) {
            int col = n0 + wn * 64 + ni * 8 + tig * 2;
            *(float2*)(g_v + (size_t)r0 * DIM + col) =
                make_float2(acc[mi][ni][0], acc[mi][ni][1]);
            *(float2*)(g_v + (size_t)(r0 + 8) * DIM + col) =
                make_float2(acc[mi][ni][2], acc[mi][ni][3]);
        }
    }
}

// ------------- k_g: per-(bh) max, g_t = exp(st-m*), r_t = 1/cumsum(g) ----
__global__ __launch_bounds__(128) void k_g() {
    int bh = blockIdx.x;                 // 64
    int tid = threadIdx.x;               // 128, each owns 16 consecutive t
    const float* stp = g_stT + (size_t)bh * TT;
    float s[16];
#pragma unroll
    for (int j = 0; j < 16; j++) s[j] = stp[tid * 16 + j];
    float lm = s[0];
#pragma unroll
    for (int j = 1; j < 16; j++) lm = fmaxf(lm, s[j]);
    __shared__ float sc[128];
    sc[tid] = lm;
    __syncthreads();
#pragma unroll
    for (int off = 64; off > 0; off >>= 1) {
        if (tid < off) sc[tid] = fmaxf(sc[tid], sc[tid + off]);
        __syncthreads();
    }
    float mstar = sc[0];
    __syncthreads();
    float g[16];
    float run = 0.f;
#pragma unroll
    for (int j = 0; j < 16; j++) { g[j] = __expf(s[j] - mstar); run += g[j]; }
    sc[tid] = run;
    __syncthreads();
#pragma unroll
    for (int off = 1; off < 128; off <<= 1) {
        float v = (tid >= off) ? sc[tid - off] : 0.f;
        __syncthreads();
        sc[tid] += v;
        __syncthreads();
    }
    float cum = (tid == 0) ? 0.f : sc[tid - 1];   // exclusive, additions-only
    float* gg = g_gq + (size_t)bh * TT + tid * 16;
    float* gr = g_rq + (size_t)bh * TT + tid * 16;
#pragma unroll
    for (int j = 0; j < 16; j++) {
        cum += g[j];
        gg[j] = g[j];
        gr[j] = __fdividef(1.f, fmaxf(cum, 1e-37f));
    }
}

// ------------- k_w1: chunk sums of v*g over 64-row chunks ----------------
__global__ __launch_bounds__(512) void k_w1() {
    int c = blockIdx.x;                  // 32
    int hq = blockIdx.y;                 // 2
    int b = blockIdx.z;                  // 4
    int tid = threadIdx.x;               // 512: hh(8) x d(64)
    int hh = tid >> 6, d = tid & 63;
    __shared__ float gs[8][64];
    gs[hh][d] = g_gq[(size_t)(b * HH + hq * 8 + hh) * TT + c * WCH + d];
    __syncthreads();
    int row0 = b * TT + c * WCH;
    const float* vp = g_v + (size_t)row0 * DIM + (hq * 8 + hh) * DD + d;
    float w = 0.f;
#pragma unroll 8
    for (int t = 0; t < WCH; t++) w += vp[(size_t)t * DIM] * gs[hh][t];
    g_ws[((b * NWC + c) << 10) + (hq * 8 + hh) * DD + d] = w;
}

// ------------- k_w3: chunk prefix + cumsum + h = w*r, fused head-mean ----
__global__ __launch_bounds__(1024) void k_w3() {
    int c = blockIdx.x;                  // 32
    int b = blockIdx.y;                  // 4
    int tid = threadIdx.x;               // 1024 = h*64+d
    int h = tid >> 6, d = tid & 63;
    __shared__ float gs[16][64];
    __shared__ float rs[16][64];
    __shared__ float red[4][16][65];     // 4-t batch, padded
    __shared__ float red2[4][4][68];     // partial head sums
    gs[h][d] = g_gq[(size_t)(b * HH + h) * TT + c * WCH + d];
    rs[h][d] = g_rq[(size_t)(b * HH + h) * TT + c * WCH + d];
    // exclusive chunk prefix computed in-place (same order as old k_w2)
    float w = 0.f;
    for (int cc = 0; cc < c; cc++) w += g_ws[((b * NWC + cc) << 10) + tid];
    int row0 = b * TT + c * WCH;
    const float* vp = g_v + (size_t)row0 * DIM + tid;
    __syncthreads();

    int k2 = tid >> 8;                   // 0..3 (t within batch)
    int hq = (tid >> 6) & 3;             // 0..3 (head quarter)
    int d2 = tid & 63;

    float vbuf[2][4];
#pragma unroll
    for (int k = 0; k < 4; k++) vbuf[0][k] = vp[(size_t)k * DIM];

    for (int t = 0; t < WCH; t += 4) {
        int cur = (t >> 2) & 1, nxt = cur ^ 1;
        if (t + 4 < WCH) {
#pragma unroll
            for (int k = 0; k < 4; k++) vbuf[nxt][k] = vp[(size_t)(t + 4 + k) * DIM];
        }
#pragma unroll
        for (int k = 0; k < 4; k++) {
            int tt = t + k;
            w += vbuf[cur][k] * gs[h][tt];
            red[k][h][d] = w * rs[h][tt];
        }
        __syncthreads();
        float p = red[k2][hq * 4 + 0][d2] + red[k2][hq * 4 + 1][d2]
                + red[k2][hq * 4 + 2][d2] + red[k2][hq * 4 + 3][d2];
        red2[k2][hq][d2] = p;
        __syncthreads();
        if (tid < 256) {
            int kk = tid >> 6, dd = tid & 63;
            float s = red2[kk][0][dd] + red2[kk][1][dd]
                    + red2[kk][2][dd] + red2[kk][3][dd];
            g_hmean[(size_t)(row0 + t + kk) * DD + dd] = s * 0.0625f;
        }
        __syncthreads();
    }
}

// ---------------- output GEMM: out = hmean @ out_w^T + b -----------------
__global__ void gemm_out(const float* __restrict__ out_w,
                         const float* __restrict__ out_b,
                         float* __restrict__ out) {
    __shared__ float Hs[64][65];
    __shared__ float Ws[64][68];
    int m0 = blockIdx.y * 64, n0 = blockIdx.x * 64;
    int tid = threadIdx.x;
    const float* hsrc = g_hmean + (size_t)m0 * DD;
    for (int i = tid; i < 64 * 64; i += 256) Hs[i >> 6][i & 63] = hsrc[i];
    for (int i = tid; i < 64 * 64; i += 256) {
        int o = i >> 6, d = i & 63;
        Ws[d][o] = out_w[(size_t)(n0 + o) * DD + d];
    }
    __syncthreads();
    int tr = tid >> 4, tc = tid & 15;
    float acc[4][4];
#pragma unroll
    for (int i = 0; i < 4; i++)
#pragma unroll
        for (int j = 0; j < 4; j++) acc[i][j] = 0.f;
#pragma unroll 8
    for (int k = 0; k < 64; k++) {
        float a[4], bv[4];
#pragma unroll
        for (int i = 0; i < 4; i++) a[i] = Hs[tr * 4 + i][k];
#pragma unroll
        for (int j = 0; j < 4; j++) bv[j] = Ws[k][tc * 4 + j];
#pragma unroll
        for (int i = 0; i < 4; i++)
#pragma unroll
            for (int j = 0; j < 4; j++) acc[i][j] += a[i] * bv[j];
    }
    float bo[4];
#pragma unroll
    for (int j = 0; j < 4; j++) bo[j] = out_b[n0 + tc * 4 + j];
#pragma unroll
    for (int i = 0; i < 4; i++) {
        float4 v4 = make_float4(acc[i][0] + bo[0], acc[i][1] + bo[1],
                                acc[i][2] + bo[2], acc[i][3] + bo[3]);
        *(float4*)(out + (size_t)(m0 + tr * 4 + i) * DOUT + n0 + tc * 4) = v4;
    }
}

// ---------------- launch -------------------------------------------------
extern "C" void kernel_launch(void* const* d_in, const int* in_sizes, int n_in,
                              void* d_out, int out_size) {
    const float* x    = (const float*)d_in[0];   // [4,2048,1024]
    const float* kvk  = (const float*)d_in[1];   // [1024,16,64,2]
    const float* q    = (const float*)d_in[2];   // [16,64]
    const float* outw = (const float*)d_in[3];   // [1024,64]
    const float* outb = (const float*)d_in[4];   // [1024]
    float* out = (float*)d_out;                  // [4,2048,1024]

    cudaFuncSetAttribute(gemm_vst, cudaFuncAttributeMaxDynamicSharedMemorySize,
                         GV_SMEM_TOTAL);

    pack_all<<<2048 + 1024 + 64, 256>>>(x, kvk, q);
    gemm_vst<<<dim3(9, BT / GV_TM), 128, GV_SMEM_TOTAL>>>();
    k_g<<<NBH, 128>>>();
    k_w1<<<dim3(NWC, 2, BB), 512>>>();
    k_w3<<<dim3(NWC, BB), 1024>>>();
    gemm_out<<<dim3(DOUT / 64, BT / 64), 256>>>(outw, outb, out);
}